// round 3
// baseline (speedup 1.0000x reference)
#include <cuda_runtime.h>
#include <cstdint>
#include <cstdio>

#define N_NODES 131072
#define KNBR    27
#define FIN     3
#define FOUT    32

// 16 MB scratch for intermediate h (post BN+SiLU, pre-rounded to tf32 bits).
__device__ float g_h[N_NODES * FOUT];

__device__ __forceinline__ uint32_t f2tf32(float x) {
    uint32_t r;
    asm("cvt.rna.tf32.f32 %0, %1;" : "=r"(r) : "f"(x));
    return r;
}

__device__ __forceinline__ void mma_tf32(float d[4], const uint32_t a[4],
                                         const uint32_t b[2], const float c[4]) {
    asm volatile(
        "mma.sync.aligned.m16n8k8.row.col.f32.tf32.tf32.f32 "
        "{%0,%1,%2,%3}, {%4,%5,%6,%7}, {%8,%9}, {%10,%11,%12,%13};"
        : "=f"(d[0]), "=f"(d[1]), "=f"(d[2]), "=f"(d[3])
        : "r"(a[0]), "r"(a[1]), "r"(a[2]), "r"(a[3]),
          "r"(b[0]), "r"(b[1]),
          "f"(c[0]), "f"(c[1]), "f"(c[2]), "f"(c[3]));
}

// ---------------------------------------------------------------------------
// Stage 1: h[n,o] = sum_{k,f} x[nbr[n,k],f] * w1[k,f,o]; then BN + SiLU.
// Persistent: 148 blocks x 512 threads; chunk = 512 nodes; warp owns 32 nodes
// (two m16 tiles). K padded 3->8 with zeros (a2=a3=0, b1=0, col3 of b0 zero).
// ---------------------------------------------------------------------------
__global__ __launch_bounds__(512) void stage1_kernel(
    const float* __restrict__ x, const int* __restrict__ nbr,
    const float* __restrict__ w1,
    const float* __restrict__ bg, const float* __restrict__ bb,
    const float* __restrict__ bm, const float* __restrict__ bv)
{
    extern __shared__ char smem[];
    int*      nbr_s = (int*)smem;                                   // 512*27*4   = 55296 B
    uint32_t* w1s   = (uint32_t*)(smem + 512 * KNBR * 4);           // 27*32*4*4  = 13824 B
    float*    sc    = (float*)(smem + 512 * KNBR * 4 + KNBR*32*4*4);// 32 floats
    float*    sh    = sc + 32;                                      // 32 floats

    const int tid = threadIdx.x;

    // w1s[k][o][c] (c in 0..3, col3 zero-padded), tf32-rounded.
    for (int i = tid; i < KNBR * 32 * 4; i += blockDim.x) {
        int k = i >> 7, o = (i >> 2) & 31, c = i & 3;
        float v = (c < FIN) ? w1[(k * FIN + c) * FOUT + o] : 0.0f;
        w1s[i] = f2tf32(v);
    }
    if (tid < 32) {
        float s = bg[tid] * rsqrtf(bv[tid] + 1e-5f);
        sc[tid] = s;
        sh[tid] = bb[tid] - bm[tid] * s;
    }

    const int warp = tid >> 5, lane = tid & 31;
    const int g = lane >> 2, c4 = lane & 3;

    for (int chunk = blockIdx.x; chunk < N_NODES / 512; chunk += gridDim.x) {
        const int nbase = chunk * 512;
        __syncthreads();   // protect nbr_s reuse
        for (int i = tid; i < 512 * KNBR; i += blockDim.x)
            nbr_s[i] = nbr[nbase * KNBR + i];
        __syncthreads();

        float acc[2][4][4];
        #pragma unroll
        for (int t = 0; t < 2; t++)
            #pragma unroll
            for (int nf = 0; nf < 4; nf++)
                #pragma unroll
                for (int i = 0; i < 4; i++) acc[t][nf][i] = 0.0f;

        for (int k = 0; k < KNBR; k++) {
            uint32_t b0f[4];
            #pragma unroll
            for (int nf = 0; nf < 4; nf++)
                b0f[nf] = w1s[((k * 32 + nf * 8 + g) << 2) + c4];
            #pragma unroll
            for (int t = 0; t < 2; t++) {
                int ln = warp * 32 + t * 16 + g;
                int r0 = nbr_s[ln * KNBR + k];
                int r1 = nbr_s[(ln + 8) * KNBR + k];
                uint32_t a[4];
                a[0] = (c4 < FIN) ? f2tf32(x[r0 * FIN + c4]) : 0u;
                a[1] = (c4 < FIN) ? f2tf32(x[r1 * FIN + c4]) : 0u;
                a[2] = 0u; a[3] = 0u;
                #pragma unroll
                for (int nf = 0; nf < 4; nf++) {
                    uint32_t b[2] = { b0f[nf], 0u };
                    mma_tf32(acc[t][nf], a, b, acc[t][nf]);
                }
            }
        }

        // Epilogue: BN + SiLU, store pre-rounded tf32 bits into g_h.
        #pragma unroll
        for (int t = 0; t < 2; t++) {
            #pragma unroll
            for (int nf = 0; nf < 4; nf++) {
                #pragma unroll
                for (int i = 0; i < 4; i++) {
                    int o = nf * 8 + 2 * c4 + (i & 1);
                    int n = nbase + warp * 32 + t * 16 + g + ((i >> 1) << 3);
                    float v = acc[t][nf][i] * sc[o] + sh[o];
                    float s = v * (1.0f / (1.0f + __expf(-v)));
                    g_h[n * FOUT + o] = __uint_as_float(f2tf32(s));
                }
            }
        }
    }
}

// ---------------------------------------------------------------------------
// Stage 2: x_out[n,o] = sum_{k,c} h[nbr[n,k],c] * w2[k,c,o];
// plus point branch z = relu(bn(z_feats @ mlp_w + mlp_b)); out = x_out + z
// written twice (reference returns (fused, fused)).
// w2 smem layout: w2s[k][o][cpad=36] -> B-fragment LDS is bank-conflict-free
// (bank = (o*4 + c) % 32 == laneid).
// ---------------------------------------------------------------------------
__global__ __launch_bounds__(512) void stage2_kernel(
    const int* __restrict__ nbr,
    const float* __restrict__ w2,
    const float* __restrict__ zf,
    const float* __restrict__ mlpw, const float* __restrict__ mlpb,
    const float* __restrict__ mg, const float* __restrict__ mb2,
    const float* __restrict__ mm, const float* __restrict__ mv,
    float* __restrict__ out)
{
    extern __shared__ char smem[];
    int*      nbr_s = (int*)smem;                          // 55296 B
    uint32_t* w2s   = (uint32_t*)(smem + 55296);           // 27*32*36*4 = 124416 B
    float*    mw_s  = (float*)(smem + 55296 + 124416);     // 96 floats
    float*    pA    = mw_s + 96;                           // 32
    float*    pB    = pA + 32;                             // 32

    const int tid = threadIdx.x;

    for (int i = tid; i < KNBR * FOUT * FOUT; i += blockDim.x) {
        int k = i >> 10, c = (i >> 5) & 31, o = i & 31;
        w2s[(k * 32 + o) * 36 + c] = f2tf32(w2[i]);
    }
    for (int i = tid; i < FIN * FOUT; i += blockDim.x) mw_s[i] = mlpw[i];
    if (tid < 32) {
        float s = mg[tid] * rsqrtf(mv[tid] + 1e-5f);
        pA[tid] = s;
        pB[tid] = mlpb[tid] * s + mb2[tid] - mm[tid] * s;
    }

    const uint32_t* hu = (const uint32_t*)g_h;
    const int warp = tid >> 5, lane = tid & 31;
    const int g = lane >> 2, c4 = lane & 3;

    for (int chunk = blockIdx.x; chunk < N_NODES / 512; chunk += gridDim.x) {
        const int nbase = chunk * 512;
        __syncthreads();
        for (int i = tid; i < 512 * KNBR; i += blockDim.x)
            nbr_s[i] = nbr[nbase * KNBR + i];
        __syncthreads();

        float acc[2][4][4];
        #pragma unroll
        for (int t = 0; t < 2; t++)
            #pragma unroll
            for (int nf = 0; nf < 4; nf++)
                #pragma unroll
                for (int i = 0; i < 4; i++) acc[t][nf][i] = 0.0f;

        for (int k = 0; k < KNBR; k++) {
            uint32_t bfr[4][4][2];
            #pragma unroll
            for (int j = 0; j < 4; j++)
                #pragma unroll
                for (int nf = 0; nf < 4; nf++) {
                    int idx = (k * 32 + nf * 8 + g) * 36 + j * 8 + c4;
                    bfr[j][nf][0] = w2s[idx];
                    bfr[j][nf][1] = w2s[idx + 4];
                }
            #pragma unroll
            for (int t = 0; t < 2; t++) {
                int ln = warp * 32 + t * 16 + g;
                int r0 = nbr_s[ln * KNBR + k] * FOUT;
                int r1 = nbr_s[(ln + 8) * KNBR + k] * FOUT;
                #pragma unroll
                for (int j = 0; j < 4; j++) {
                    uint32_t a[4];
                    a[0] = hu[r0 + j * 8 + c4];
                    a[1] = hu[r1 + j * 8 + c4];
                    a[2] = hu[r0 + j * 8 + c4 + 4];
                    a[3] = hu[r1 + j * 8 + c4 + 4];
                    #pragma unroll
                    for (int nf = 0; nf < 4; nf++)
                        mma_tf32(acc[t][nf], a, bfr[j][nf], acc[t][nf]);
                }
            }
        }

        // Epilogue: point branch + fuse, write both output copies (STG.64).
        #pragma unroll
        for (int t = 0; t < 2; t++) {
            int n0 = nbase + warp * 32 + t * 16 + g;
            float z00 = zf[n0 * 3], z01 = zf[n0 * 3 + 1], z02 = zf[n0 * 3 + 2];
            float z10 = zf[(n0 + 8) * 3], z11 = zf[(n0 + 8) * 3 + 1], z12 = zf[(n0 + 8) * 3 + 2];
            #pragma unroll
            for (int nf = 0; nf < 4; nf++) {
                int o0 = nf * 8 + 2 * c4;
                float w0a = mw_s[o0],      w1a = mw_s[32 + o0],      w2a = mw_s[64 + o0];
                float w0b = mw_s[o0 + 1],  w1b = mw_s[32 + o0 + 1],  w2b = mw_s[64 + o0 + 1];
                float sA0 = pA[o0], sB0 = pB[o0], sA1 = pA[o0 + 1], sB1 = pB[o0 + 1];

                float d0 = z00 * w0a + z01 * w1a + z02 * w2a;
                float d1 = z00 * w0b + z01 * w1b + z02 * w2b;
                float e0 = z10 * w0a + z11 * w1a + z12 * w2a;
                float e1 = z10 * w0b + z11 * w1b + z12 * w2b;

                float2 lo, hi;
                lo.x = acc[t][nf][0] + fmaxf(d0 * sA0 + sB0, 0.0f);
                lo.y = acc[t][nf][1] + fmaxf(d1 * sA1 + sB1, 0.0f);
                hi.x = acc[t][nf][2] + fmaxf(e0 * sA0 + sB0, 0.0f);
                hi.y = acc[t][nf][3] + fmaxf(e1 * sA1 + sB1, 0.0f);

                size_t half = (size_t)N_NODES * FOUT;
                *(float2*)(out + (size_t)n0 * FOUT + o0)        = lo;
                *(float2*)(out + half + (size_t)n0 * FOUT + o0) = lo;
                *(float2*)(out + (size_t)(n0 + 8) * FOUT + o0)        = hi;
                *(float2*)(out + half + (size_t)(n0 + 8) * FOUT + o0) = hi;
            }
        }
    }
}

// ---------------------------------------------------------------------------

extern "C" void kernel_launch(void* const* d_in, const int* in_sizes, int n_in,
                              void* d_out, int out_size) {
    (void)in_sizes; (void)n_in; (void)out_size;
    const float* x    = (const float*)d_in[0];
    const float* z    = (const float*)d_in[1];
    const int*   nbr  = (const int*)  d_in[2];
    const float* w1   = (const float*)d_in[3];
    const float* bg   = (const float*)d_in[4];
    const float* bb   = (const float*)d_in[5];
    const float* bm   = (const float*)d_in[6];
    const float* bv   = (const float*)d_in[7];
    const float* w2   = (const float*)d_in[8];
    const float* mlpw = (const float*)d_in[9];
    const float* mlpb = (const float*)d_in[10];
    const float* mg   = (const float*)d_in[11];
    const float* mb2  = (const float*)d_in[12];
    const float* mm   = (const float*)d_in[13];
    const float* mv   = (const float*)d_in[14];
    float* out = (float*)d_out;

    const int smem1 = 512 * KNBR * 4 + KNBR * 32 * 4 * 4 + 64 * 4;       // 69376 B
    const int smem2 = 55296 + 124416 + (96 + 64) * 4;                    // 180352 B

    cudaFuncSetAttribute(stage1_kernel, cudaFuncAttributeMaxDynamicSharedMemorySize, smem1);
    cudaFuncSetAttribute(stage2_kernel, cudaFuncAttributeMaxDynamicSharedMemorySize, smem2);

    stage1_kernel<<<148, 512, smem1>>>(x, nbr, w1, bg, bb, bm, bv);
    stage2_kernel<<<148, 512, smem2>>>(nbr, w2, z, mlpw, mlpb, mg, mb2, mm, mv, out);
}

// round 4
// speedup vs baseline: 2.1173x; 2.1173x over previous
#include <cuda_runtime.h>
#include <cuda_fp16.h>
#include <cstdint>

#define N_NODES 131072
#define KNBR    27
#define FIN     3
#define FOUT    32

// 8 MB scratch: intermediate h (post BN+SiLU), fp16, fragment-permuted per row:
// g_h[n*32 + perm32(c)] = h[n][c],  perm32(c) = ((c>>1)&3)*8 + ((c>>3)<<1) + (c&1)
// => lane c4 of a warp reads its whole m16n8k16 A-fragment slice of a row as ONE
//    contiguous 16B chunk at byte offset c4*16 within the 64B row.
__device__ __half g_h[N_NODES * FOUT];

__device__ __forceinline__ int perm32(int c) {
    return ((c >> 1) & 3) * 8 + ((c >> 3) << 1) + (c & 1);
}

__device__ __forceinline__ uint32_t f2tf32(float x) {
    uint32_t r;
    asm("cvt.rna.tf32.f32 %0, %1;" : "=r"(r) : "f"(x));
    return r;
}

__device__ __forceinline__ void mma_tf32(float d[4], const uint32_t a[4],
                                         const uint32_t b[2]) {
    asm volatile(
        "mma.sync.aligned.m16n8k8.row.col.f32.tf32.tf32.f32 "
        "{%0,%1,%2,%3}, {%4,%5,%6,%7}, {%8,%9}, {%0,%1,%2,%3};"
        : "+f"(d[0]), "+f"(d[1]), "+f"(d[2]), "+f"(d[3])
        : "r"(a[0]), "r"(a[1]), "r"(a[2]), "r"(a[3]),
          "r"(b[0]), "r"(b[1]));
}

__device__ __forceinline__ void mma_f16(float d[4],
                                        uint32_t a0, uint32_t a1, uint32_t a2, uint32_t a3,
                                        uint32_t b0, uint32_t b1) {
    asm volatile(
        "mma.sync.aligned.m16n8k16.row.col.f32.f16.f16.f32 "
        "{%0,%1,%2,%3}, {%4,%5,%6,%7}, {%8,%9}, {%0,%1,%2,%3};"
        : "+f"(d[0]), "+f"(d[1]), "+f"(d[2]), "+f"(d[3])
        : "r"(a0), "r"(a1), "r"(a2), "r"(a3), "r"(b0), "r"(b1));
}

// ---------------------------------------------------------------------------
// Stage 1: h[n,o] = sum_{k,f} x[nbr[n,k],f] * w1[k,f,o]; BN + SiLU.
// tf32 mma (K padded 3->8). Epilogue: per-warp smem transpose -> fp16 permuted
// g_h written with fully coalesced STG.128.
// ---------------------------------------------------------------------------
#define S1_NBR   0
#define S1_W1    (512 * KNBR * 4)                 // 55296
#define S1_SC    (S1_W1 + KNBR * 32 * 4 * 4)      // +13824 = 69120
#define S1_SH    (S1_SC + 128)
#define S1_BUF   (S1_SH + 128)                    // 69376, 16B aligned
#define S1_SMEM  (S1_BUF + 16 * 2048)             // 102144

__global__ __launch_bounds__(512) void stage1_kernel(
    const float* __restrict__ x, const int* __restrict__ nbr,
    const float* __restrict__ w1,
    const float* __restrict__ bg, const float* __restrict__ bb,
    const float* __restrict__ bm, const float* __restrict__ bv)
{
    extern __shared__ char smem[];
    int*      nbr_s = (int*)(smem + S1_NBR);
    uint32_t* w1s   = (uint32_t*)(smem + S1_W1);
    float*    sc    = (float*)(smem + S1_SC);
    float*    sh    = (float*)(smem + S1_SH);

    const int tid = threadIdx.x;

    // w1s[k][o][c] (c 0..3, col3 zero), tf32-rounded.
    for (int i = tid; i < KNBR * 32 * 4; i += blockDim.x) {
        int k = i >> 7, o = (i >> 2) & 31, c = i & 3;
        float v = (c < FIN) ? w1[(k * FIN + c) * FOUT + o] : 0.0f;
        w1s[i] = f2tf32(v);
    }
    if (tid < 32) {
        float s = bg[tid] * rsqrtf(bv[tid] + 1e-5f);
        sc[tid] = s;
        sh[tid] = bb[tid] - bm[tid] * s;
    }

    const int warp = tid >> 5, lane = tid & 31;
    const int g = lane >> 2, c4 = lane & 3;
    __half* buf = (__half*)(smem + S1_BUF) + warp * 1024;

    for (int chunk = blockIdx.x; chunk < N_NODES / 512; chunk += gridDim.x) {
        const int nbase = chunk * 512;
        __syncthreads();
        for (int i = tid; i < 512 * KNBR; i += blockDim.x)
            nbr_s[i] = nbr[nbase * KNBR + i];
        __syncthreads();

        float acc[2][4][4];
        #pragma unroll
        for (int t = 0; t < 2; t++)
            #pragma unroll
            for (int nf = 0; nf < 4; nf++)
                #pragma unroll
                for (int i = 0; i < 4; i++) acc[t][nf][i] = 0.0f;

        for (int k = 0; k < KNBR; k++) {
            uint32_t b0f[4];
            #pragma unroll
            for (int nf = 0; nf < 4; nf++)
                b0f[nf] = w1s[((k * 32 + nf * 8 + g) << 2) + c4];
            #pragma unroll
            for (int t = 0; t < 2; t++) {
                int ln = warp * 32 + t * 16 + g;
                int r0 = nbr_s[ln * KNBR + k];
                int r1 = nbr_s[(ln + 8) * KNBR + k];
                uint32_t a[4];
                a[0] = (c4 < FIN) ? f2tf32(x[r0 * FIN + c4]) : 0u;
                a[1] = (c4 < FIN) ? f2tf32(x[r1 * FIN + c4]) : 0u;
                a[2] = 0u; a[3] = 0u;
                #pragma unroll
                for (int nf = 0; nf < 4; nf++) {
                    uint32_t b[2] = { b0f[nf], 0u };
                    mma_tf32(acc[t][nf], a, b);
                }
            }
        }

        // Epilogue: BN + SiLU -> fp16 permuted into per-warp smem tile,
        // then coalesced 16B copies into g_h (32 nodes x 64B contiguous).
        #pragma unroll
        for (int t = 0; t < 2; t++)
            #pragma unroll
            for (int nf = 0; nf < 4; nf++)
                #pragma unroll
                for (int i = 0; i < 4; i++) {
                    int o  = nf * 8 + 2 * c4 + (i & 1);
                    int nl = t * 16 + g + ((i >> 1) << 3);
                    float v = acc[t][nf][i] * sc[o] + sh[o];
                    float s = v * (1.0f / (1.0f + __expf(-v)));
                    buf[nl * 32 + perm32(o)] = __float2half_rn(s);
                }
        __syncwarp();
        uint4* dst = (uint4*)(g_h + (size_t)(nbase + warp * 32) * FOUT);
        const uint4* src = (const uint4*)buf;
        #pragma unroll
        for (int m = 0; m < 4; m++) dst[m * 32 + lane] = src[m * 32 + lane];
        __syncwarp();
    }
}

// ---------------------------------------------------------------------------
// Stage 2: x_out[n,o] = sum_{k,c} h[nbr[n,k],c] * w2[k,c,o]  (fp16 m16n8k16)
// + point branch, fused output written twice.
// w2 in smem: dense fragment-permuted [k][o][32 halves], lane c4 reads one
// LDS.128 per (k,o-tile): quad index (4o + c4) mod 8 -> conflict-free.
// A gathers: one LDG.128 per gathered row (64B rows, permuted fp16).
// Software-pipelined: prefetch k+1's A while computing k.
// ---------------------------------------------------------------------------
#define S2_NBR  0
#define S2_W2   (512 * KNBR * 4)        // 55296 (16B aligned)
#define S2_MW   (S2_W2 + KNBR * 32 * 32 * 2)  // +55296 = 110592
#define S2_PA   (S2_MW + 96 * 4)
#define S2_PB   (S2_PA + 128)
#define S2_SMEM (S2_PB + 128)           // 111232

__global__ __launch_bounds__(512) void stage2_kernel(
    const int* __restrict__ nbr,
    const float* __restrict__ w2,
    const float* __restrict__ zf,
    const float* __restrict__ mlpw, const float* __restrict__ mlpb,
    const float* __restrict__ mg, const float* __restrict__ mb2,
    const float* __restrict__ mm, const float* __restrict__ mv,
    float* __restrict__ out)
{
    extern __shared__ char smem[];
    int*    nbr_s = (int*)(smem + S2_NBR);
    __half* w2h   = (__half*)(smem + S2_W2);
    float*  mw_s  = (float*)(smem + S2_MW);
    float*  pA    = (float*)(smem + S2_PA);
    float*  pB    = (float*)(smem + S2_PB);

    const int tid = threadIdx.x;

    for (int i = tid; i < KNBR * FOUT * FOUT; i += blockDim.x) {
        int k = i >> 10, c = (i >> 5) & 31, o = i & 31;
        w2h[(k * 32 + o) * 32 + perm32(c)] = __float2half_rn(w2[i]);
    }
    for (int i = tid; i < FIN * FOUT; i += blockDim.x) mw_s[i] = mlpw[i];
    if (tid < 32) {
        float s = mg[tid] * rsqrtf(mv[tid] + 1e-5f);
        pA[tid] = s;
        pB[tid] = mlpb[tid] * s + mb2[tid] - mm[tid] * s;
    }

    const uint4* h4  = (const uint4*)g_h;   // row r = 4 x uint4 (64B)
    const uint4* w2v = (const uint4*)w2h;
    const int warp = tid >> 5, lane = tid & 31;
    const int g = lane >> 2, c4 = lane & 3;

#define LOADA(kk, AB) { \
    _Pragma("unroll") \
    for (int t = 0; t < 2; t++) { \
        int ln = warp * 32 + t * 16 + g; \
        int r0 = nbr_s[ln * KNBR + (kk)]; \
        int r1 = nbr_s[(ln + 8) * KNBR + (kk)]; \
        AB[t][0] = h4[r0 * 4 + c4]; \
        AB[t][1] = h4[r1 * 4 + c4]; \
    } }

#define COMPUTE(kk, AB) { \
    uint4 W[4]; \
    _Pragma("unroll") \
    for (int nf = 0; nf < 4; nf++) \
        W[nf] = w2v[(((kk) * 32 + nf * 8 + g) << 2) + c4]; \
    _Pragma("unroll") \
    for (int t = 0; t < 2; t++) { \
        _Pragma("unroll") \
        for (int nf = 0; nf < 4; nf++) { \
            mma_f16(acc[t][nf], AB[t][0].x, AB[t][1].x, AB[t][0].y, AB[t][1].y, \
                    W[nf].x, W[nf].y); \
            mma_f16(acc[t][nf], AB[t][0].z, AB[t][1].z, AB[t][0].w, AB[t][1].w, \
                    W[nf].z, W[nf].w); \
        } } }

    for (int chunk = blockIdx.x; chunk < N_NODES / 512; chunk += gridDim.x) {
        const int nbase = chunk * 512;
        __syncthreads();
        for (int i = tid; i < 512 * KNBR; i += blockDim.x)
            nbr_s[i] = nbr[nbase * KNBR + i];
        __syncthreads();

        float acc[2][4][4];
        #pragma unroll
        for (int t = 0; t < 2; t++)
            #pragma unroll
            for (int nf = 0; nf < 4; nf++)
                #pragma unroll
                for (int i = 0; i < 4; i++) acc[t][nf][i] = 0.0f;

        uint4 Ab0[2][2], Ab1[2][2];
        LOADA(0, Ab0);
        #pragma unroll 1
        for (int k = 0; k < KNBR - 1; k += 2) {
            LOADA(k + 1, Ab1);
            COMPUTE(k, Ab0);
            LOADA(k + 2, Ab0);
            COMPUTE(k + 1, Ab1);
        }
        COMPUTE(KNBR - 1, Ab0);

        // Epilogue: point branch + fuse; write both output copies.
        #pragma unroll
        for (int t = 0; t < 2; t++) {
            int n0 = nbase + warp * 32 + t * 16 + g;
            float z00 = zf[n0 * 3], z01 = zf[n0 * 3 + 1], z02 = zf[n0 * 3 + 2];
            float z10 = zf[(n0 + 8) * 3], z11 = zf[(n0 + 8) * 3 + 1], z12 = zf[(n0 + 8) * 3 + 2];
            #pragma unroll
            for (int nf = 0; nf < 4; nf++) {
                int o0 = nf * 8 + 2 * c4;
                float w0a = mw_s[o0],     w1a = mw_s[32 + o0],     w2a = mw_s[64 + o0];
                float w0b = mw_s[o0 + 1], w1b = mw_s[32 + o0 + 1], w2b = mw_s[64 + o0 + 1];
                float sA0 = pA[o0], sB0 = pB[o0], sA1 = pA[o0 + 1], sB1 = pB[o0 + 1];

                float d0 = z00 * w0a + z01 * w1a + z02 * w2a;
                float d1 = z00 * w0b + z01 * w1b + z02 * w2b;
                float e0 = z10 * w0a + z11 * w1a + z12 * w2a;
                float e1 = z10 * w0b + z11 * w1b + z12 * w2b;

                float2 lo, hi;
                lo.x = acc[t][nf][0] + fmaxf(d0 * sA0 + sB0, 0.0f);
                lo.y = acc[t][nf][1] + fmaxf(d1 * sA1 + sB1, 0.0f);
                hi.x = acc[t][nf][2] + fmaxf(e0 * sA0 + sB0, 0.0f);
                hi.y = acc[t][nf][3] + fmaxf(e1 * sA1 + sB1, 0.0f);

                size_t half = (size_t)N_NODES * FOUT;
                *(float2*)(out + (size_t)n0 * FOUT + o0)              = lo;
                *(float2*)(out + half + (size_t)n0 * FOUT + o0)       = lo;
                *(float2*)(out + (size_t)(n0 + 8) * FOUT + o0)        = hi;
                *(float2*)(out + half + (size_t)(n0 + 8) * FOUT + o0) = hi;
            }
        }
    }
#undef LOADA
#undef COMPUTE
}

// ---------------------------------------------------------------------------

extern "C" void kernel_launch(void* const* d_in, const int* in_sizes, int n_in,
                              void* d_out, int out_size) {
    (void)in_sizes; (void)n_in; (void)out_size;
    const float* x    = (const float*)d_in[0];
    const float* z    = (const float*)d_in[1];
    const int*   nbr  = (const int*)  d_in[2];
    const float* w1   = (const float*)d_in[3];
    const float* bg   = (const float*)d_in[4];
    const float* bb   = (const float*)d_in[5];
    const float* bm   = (const float*)d_in[6];
    const float* bv   = (const float*)d_in[7];
    const float* w2   = (const float*)d_in[8];
    const float* mlpw = (const float*)d_in[9];
    const float* mlpb = (const float*)d_in[10];
    const float* mg   = (const float*)d_in[11];
    const float* mb2  = (const float*)d_in[12];
    const float* mm   = (const float*)d_in[13];
    const float* mv   = (const float*)d_in[14];
    float* out = (float*)d_out;

    cudaFuncSetAttribute(stage1_kernel, cudaFuncAttributeMaxDynamicSharedMemorySize, S1_SMEM);
    cudaFuncSetAttribute(stage2_kernel, cudaFuncAttributeMaxDynamicSharedMemorySize, S2_SMEM);

    stage1_kernel<<<148, 512, S1_SMEM>>>(x, nbr, w1, bg, bb, bm, bv);
    stage2_kernel<<<148, 512, S2_SMEM>>>(nbr, w2, z, mlpw, mlpb, mg, mb2, mm, mv, out);
}